// round 1
// baseline (speedup 1.0000x reference)
#include <cuda_runtime.h>
#include <cuda_fp16.h>

#define B    64
#define NIN  2048
#define DIN  8
#define NOUT 32
#define DOUT 16
#define OD   512   // NOUT*DOUT

// Scratch (device globals: allocation-free at run time)
__device__ __half g_preds[(size_t)B * NIN * OD];   // 128 MB, fp16 predictions
__device__ float  g_raw[B * NIN * NOUT];           // 16 MB routing logits
__device__ float  g_s[B * OD];                     // s accumulator
__device__ float  g_v[B * OD];                     // squashed v

// ---------------------------------------------------------------------------
__global__ void k_zero_s() {
    g_s[blockIdx.x * 512 + threadIdx.x] = 0.f;
}

// ---------------------------------------------------------------------------
// preds[b,n,od] = sum_i W[n,od,i] * x[b,n,i]
// One block per n (W[n] read exactly once), 128 threads, 4 od per thread held
// in registers, loop over all 64 b. fp16 stores (uint2 = 4 halves).
__global__ void k_preds(const float* __restrict__ x, const float* __restrict__ W) {
    const int n = blockIdx.x;
    const int t = threadIdx.x;          // 0..127
    __shared__ float xs[B * DIN];       // x[:, n, :]  (512 floats)
    {
        int b = t >> 1, h = t & 1;
        float4 xv = *(const float4*)(x + (b * NIN + n) * DIN + h * 4);
        *(float4*)(xs + b * DIN + h * 4) = xv;
    }
    __syncthreads();

    const float* Wn = W + (size_t)n * (NOUT * DOUT * DIN) + t * 32;  // 4 od * 8 i
    float4 w[8];
#pragma unroll
    for (int j = 0; j < 8; j++) w[j] = ((const float4*)Wn)[j];

    __half* outp = g_preds + (size_t)n * OD + t * 4;
#pragma unroll 4
    for (int b = 0; b < B; b++) {
        float4 x0 = *(float4*)(xs + b * 8);
        float4 x1 = *(float4*)(xs + b * 8 + 4);
        float r0 = w[0].x*x0.x + w[0].y*x0.y + w[0].z*x0.z + w[0].w*x0.w
                 + w[1].x*x1.x + w[1].y*x1.y + w[1].z*x1.z + w[1].w*x1.w;
        float r1 = w[2].x*x0.x + w[2].y*x0.y + w[2].z*x0.z + w[2].w*x0.w
                 + w[3].x*x1.x + w[3].y*x1.y + w[3].z*x1.z + w[3].w*x1.w;
        float r2 = w[4].x*x0.x + w[4].y*x0.y + w[4].z*x0.z + w[4].w*x0.w
                 + w[5].x*x1.x + w[5].y*x1.y + w[5].z*x1.z + w[5].w*x1.w;
        float r3 = w[6].x*x0.x + w[6].y*x0.y + w[6].z*x0.z + w[6].w*x0.w
                 + w[7].x*x1.x + w[7].y*x1.y + w[7].z*x1.z + w[7].w*x1.w;
        union { uint2 u; __half2 h[2]; } pk;
        pk.h[0] = __floats2half2_rn(r0, r1);
        pk.h[1] = __floats2half2_rn(r2, r3);
        *(uint2*)(outp + (size_t)b * NIN * OD) = pk.u;
    }
}

// ---------------------------------------------------------------------------
// Iteration 1: rw = 1/32 uniform.  s1[b,od] = (1/32) * sum_n preds[b,n,od]
// grid (8 n-chunks, 64 b), 256 threads each owning an od-pair (half2 loads).
__global__ void k_s_uniform() {
    const int b = blockIdx.y, c = blockIdx.x;
    const int t = threadIdx.x;  // 0..255
    const __half2* p = (const __half2*)g_preds + (size_t)(b * NIN + c * 256) * (OD / 2) + t;
    float acx = 0.f, acy = 0.f;
#pragma unroll 8
    for (int n = 0; n < 256; n++) {
        float2 f = __half22float2(p[(size_t)n * (OD / 2)]);
        acx += f.x; acy += f.y;
    }
    atomicAdd(&g_s[b * OD + 2 * t],     acx * (1.f / NOUT));
    atomicAdd(&g_s[b * OD + 2 * t + 1], acy * (1.f / NOUT));
}

// ---------------------------------------------------------------------------
// v = squash(s) over the D_out axis (groups of 16 lanes). Re-zeros g_s so the
// next iteration's atomic accumulation starts clean.
__global__ void k_squash(float* outv) {
    const int b = blockIdx.x, t = threadIdx.x;  // 512 threads
    float sv = g_s[b * OD + t];
    float sq = sv * sv;
    sq += __shfl_xor_sync(0xFFFFFFFFu, sq, 1);
    sq += __shfl_xor_sync(0xFFFFFFFFu, sq, 2);
    sq += __shfl_xor_sync(0xFFFFFFFFu, sq, 4);
    sq += __shfl_xor_sync(0xFFFFFFFFu, sq, 8);
    float scale = sq / ((1.f + sq) * sqrtf(sq + 1e-7f));
    float vv = scale * sv;
    g_v[b * OD + t] = vv;
    if (outv) outv[b * OD + t] = vv;
    g_s[b * OD + t] = 0.f;
}

// ---------------------------------------------------------------------------
// Fused agreement + softmax + weighted-s accumulation.
// grid (32 n-chunks, 64 b); 256 threads = 8 warps; warp handles 8 n; lane = o.
// FIRST: raw_old = 0, writes raw.  LAST: writes rw to output, no raw write.
template <bool FIRST, bool LAST>
__global__ void k_agree(float* __restrict__ out_rw) {
    const int b = blockIdx.y;
    const int warp = threadIdx.x >> 5, lane = threadIdx.x & 31;
    const int n0 = blockIdx.x * 64 + warp * 8;

    float vr[16];
    {
        const float4* vp = (const float4*)(g_v + b * OD + lane * 16);
#pragma unroll
        for (int j = 0; j < 4; j++) *(float4*)(vr + 4 * j) = vp[j];
    }
    float sp[16];
#pragma unroll
    for (int d = 0; d < 16; d++) sp[d] = 0.f;

    for (int k = 0; k < 8; k++) {
        const int n = n0 + k;
        const uint4* pp = (const uint4*)(g_preds + (size_t)(b * NIN + n) * OD) + lane * 2;
        uint4 q0 = pp[0], q1 = pp[1];
        float p[16];
        {
            union { uint4 u; __half2 h[4]; } a0, a1;
            a0.u = q0; a1.u = q1;
#pragma unroll
            for (int j = 0; j < 4; j++) {
                float2 f0 = __half22float2(a0.h[j]);
                float2 f1 = __half22float2(a1.h[j]);
                p[2 * j]     = f0.x; p[2 * j + 1]     = f0.y;
                p[8 + 2 * j] = f1.x; p[8 + 2 * j + 1] = f1.y;
            }
        }
        float a = 0.f;
#pragma unroll
        for (int d = 0; d < 16; d++) a = fmaf(p[d], vr[d], a);

        float raw = FIRST ? a : (g_raw[(b * NIN + n) * NOUT + lane] + a);
        if (!LAST) g_raw[(b * NIN + n) * NOUT + lane] = raw;

        // softmax over o = 32 lanes
        float m = raw;
#pragma unroll
        for (int s = 16; s; s >>= 1) m = fmaxf(m, __shfl_xor_sync(0xFFFFFFFFu, m, s));
        float e = __expf(raw - m);
        float es = e;
#pragma unroll
        for (int s = 16; s; s >>= 1) es += __shfl_xor_sync(0xFFFFFFFFu, es, s);
        float rw = e / es;

        if (LAST) out_rw[(b * NIN + n) * NOUT + lane] = rw;

#pragma unroll
        for (int d = 0; d < 16; d++) sp[d] = fmaf(rw, p[d], sp[d]);
    }

    // block-level reduction of s partials, then one atomicAdd per od
    __shared__ float red[8][OD];
#pragma unroll
    for (int j = 0; j < 4; j++)
        *(float4*)(&red[warp][lane * 16 + 4 * j]) = *(float4*)(sp + 4 * j);
    __syncthreads();
    for (int j = threadIdx.x; j < OD; j += 256) {
        float a = 0.f;
#pragma unroll
        for (int w = 0; w < 8; w++) a += red[w][j];
        atomicAdd(&g_s[b * OD + j], a);
    }
}

// ---------------------------------------------------------------------------
extern "C" void kernel_launch(void* const* d_in, const int* in_sizes, int n_in,
                              void* d_out, int out_size) {
    (void)in_sizes; (void)n_in; (void)out_size;
    const float* x = (const float*)d_in[0];   // [64, 2048, 8]
    const float* W = (const float*)d_in[1];   // [2048, 32, 16, 8]
    float* out = (float*)d_out;               // v (32768 floats) then rw (4194304)

    k_zero_s<<<64, 512>>>();
    k_preds<<<NIN, 128>>>(x, W);
    k_s_uniform<<<dim3(8, 64), 256>>>();          // s1 (uniform rw = 1/32)
    k_squash<<<64, 512>>>(nullptr);               // v1
    k_agree<true, false><<<dim3(32, 64), 256>>>(nullptr);   // raw2, rw2, s2
    k_squash<<<64, 512>>>(nullptr);               // v2
    k_agree<false, true><<<dim3(32, 64), 256>>>(out + B * OD);  // rw3 -> out, s3
    k_squash<<<64, 512>>>(out);                   // v3 -> out
}